// round 2
// baseline (speedup 1.0000x reference)
#include <cuda_runtime.h>
#include <cuda_bf16.h>
#include <cfloat>

// Problem constants (fixed by the reference)
#define TOK   8192
#define DIM   7168
#define NEXP  256
#define NGRP  8
#define GSZ   32      // experts per group
#define TOPKG 4
#define TOPK  8
#define RSCALE 2.5f

// Scratch: bias-added sigmoid scores s[T, E]  (8 MB, static device alloc is allowed)
__device__ float g_scores[(size_t)TOK * NEXP];

// ---------------------------------------------------------------------------
// Kernel 1: logits = X @ W^T ; s = sigmoid(logits) + bias  -> g_scores
// Classic SGEMM tiling: BM=128, BN=64, BK=16, 256 threads, 8x4 per thread.
// ---------------------------------------------------------------------------
#define BM 128
#define BN 64
#define BK 16

__global__ __launch_bounds__(256, 2)
void gemm_sigmoid_kernel(const float* __restrict__ X,
                         const float* __restrict__ W,
                         const float* __restrict__ bias,
                         float* __restrict__ S)
{
    __shared__ float As[BK][BM + 4];   // padded to dodge store conflicts
    __shared__ float Bs[BK][BN + 4];

    const int m0 = blockIdx.y * BM;
    const int n0 = blockIdx.x * BN;
    const int tid = threadIdx.x;
    const int ty = tid >> 4;           // 0..15  -> rows ty*8 .. ty*8+7
    const int tx = tid & 15;           // 0..15  -> cols tx*4 .. tx*4+3

    float acc[8][4];
#pragma unroll
    for (int i = 0; i < 8; i++)
#pragma unroll
        for (int j = 0; j < 4; j++) acc[i][j] = 0.f;

    for (int k0 = 0; k0 < DIM; k0 += BK) {
        // --- load A tile: 128 rows x 16 k = 512 float4, 2 per thread
#pragma unroll
        for (int i = 0; i < 2; i++) {
            int idx = tid + i * 256;
            int r = idx >> 2;          // 0..127
            int q = idx & 3;           // which float4 along k
            float4 v = *reinterpret_cast<const float4*>(
                X + (size_t)(m0 + r) * DIM + k0 + q * 4);
            As[q * 4 + 0][r] = v.x;
            As[q * 4 + 1][r] = v.y;
            As[q * 4 + 2][r] = v.z;
            As[q * 4 + 3][r] = v.w;
        }
        // --- load B tile: 64 rows x 16 k = 256 float4, 1 per thread
        {
            int r = tid >> 2;          // 0..63 (expert)
            int q = tid & 3;
            float4 v = *reinterpret_cast<const float4*>(
                W + (size_t)(n0 + r) * DIM + k0 + q * 4);
            Bs[q * 4 + 0][r] = v.x;
            Bs[q * 4 + 1][r] = v.y;
            Bs[q * 4 + 2][r] = v.z;
            Bs[q * 4 + 3][r] = v.w;
        }
        __syncthreads();

#pragma unroll
        for (int k = 0; k < BK; k++) {
            float a[8], b[4];
#pragma unroll
            for (int i = 0; i < 8; i++) a[i] = As[k][ty * 8 + i];
#pragma unroll
            for (int j = 0; j < 4; j++) b[j] = Bs[k][tx * 4 + j];
#pragma unroll
            for (int i = 0; i < 8; i++)
#pragma unroll
                for (int j = 0; j < 4; j++)
                    acc[i][j] = fmaf(a[i], b[j], acc[i][j]);
        }
        __syncthreads();
    }

    // epilogue: s = sigmoid(logit) + bias, write to scratch
#pragma unroll
    for (int j = 0; j < 4; j++) {
        int n = n0 + tx * 4 + j;
        float bv = bias[n];
#pragma unroll
        for (int i = 0; i < 8; i++) {
            int m = m0 + ty * 8 + i;
            float lg = acc[i][j];
            float sg = 1.0f / (1.0f + expf(-lg));
            S[(size_t)m * NEXP + n] = sg + bv;
        }
    }
}

// ---------------------------------------------------------------------------
// Kernel 2: per-token gating. One warp per token.
// Lane l owns experts [8l, 8l+8). Group g = lanes 4g..4g+3 (32 experts).
// ---------------------------------------------------------------------------
__global__ __launch_bounds__(256)
void gate_topk_kernel(const float* __restrict__ S,
                      float* __restrict__ outW,
                      float* __restrict__ outI)
{
    const unsigned FULL = 0xffffffffu;
    const int warp = threadIdx.x >> 5;
    const int lane = threadIdx.x & 31;
    const int token = blockIdx.x * 8 + warp;
    if (token >= TOK) return;

    // load this lane's 8 scores
    float v[8];
    {
        const float4* p = reinterpret_cast<const float4*>(
            S + (size_t)token * NEXP + lane * 8);
        float4 a = p[0], b = p[1];
        v[0]=a.x; v[1]=a.y; v[2]=a.z; v[3]=a.w;
        v[4]=b.x; v[5]=b.y; v[6]=b.z; v[7]=b.w;
    }

    // ---- per-lane top-2 values
    float m1 = -FLT_MAX, m2 = -FLT_MAX;
#pragma unroll
    for (int j = 0; j < 8; j++) {
        float x = v[j];
        if (x > m1) { m2 = m1; m1 = x; }
        else if (x > m2) { m2 = x; }
    }
    // ---- merge top-2 across the 4 lanes of the group (tree over offsets 2,1)
#pragma unroll
    for (int off = 2; off >= 1; off >>= 1) {
        float o1 = __shfl_down_sync(FULL, m1, off, 4);
        float o2 = __shfl_down_sync(FULL, m2, off, 4);
        float n1 = fmaxf(m1, o1);
        float n2 = fmaxf(fminf(m1, o1), fmaxf(m2, o2));
        m1 = n1; m2 = n2;
    }
    float gscore = m1 + m2;   // valid on lane 4g of each group

    // ---- every lane learns all 8 group scores, computes its own group's rank
    const int myg = lane >> 2;
    float mygs = __shfl_sync(FULL, gscore, myg * 4);
    int rank = 0;
#pragma unroll
    for (int g = 0; g < 8; g++) {
        float gs = __shfl_sync(FULL, gscore, g * 4);
        if (gs > mygs || (gs == mygs && g < myg)) rank++;
    }
    bool sel = (rank < TOPKG);

    // ---- masked scores (non-selected groups -> exactly 0.0, matching ref)
    float w[8];
#pragma unroll
    for (int j = 0; j < 8; j++) w[j] = sel ? v[j] : 0.0f;

    // ---- top-8 over 256 masked values, stable (value desc, index asc)
    for (int r = 0; r < TOPK; r++) {
        // per-lane best
        float bv = w[0]; int bi = lane * 8;
#pragma unroll
        for (int j = 1; j < 8; j++) {
            int idx = lane * 8 + j;
            if (w[j] > bv) { bv = w[j]; bi = idx; }
        }
        // warp argmax, tie -> smaller index
#pragma unroll
        for (int o = 16; o > 0; o >>= 1) {
            float ov = __shfl_xor_sync(FULL, bv, o);
            int   oi = __shfl_xor_sync(FULL, bi, o);
            if (ov > bv || (ov == bv && oi < bi)) { bv = ov; bi = oi; }
        }
        // owner lane supplies the ORIGINAL (unmasked) score and retires it
        int owner = bi >> 3;
        float orig = 0.f;
        if (lane == owner) {
            orig = v[bi & 7];
            w[bi & 7] = -FLT_MAX;
        }
        orig = __shfl_sync(FULL, orig, owner);
        if (lane == r) {
            outW[(size_t)token * TOPK + r] = orig * RSCALE;
            outI[(size_t)token * TOPK + r] = (float)bi;
        }
    }
}

// ---------------------------------------------------------------------------
extern "C" void kernel_launch(void* const* d_in, const int* in_sizes, int n_in,
                              void* d_out, int out_size)
{
    const float* x    = (const float*)d_in[0];   // [T, DIM]
    const float* wght = (const float*)d_in[1];   // [E, DIM]
    const float* bias = (const float*)d_in[2];   // [E]
    float* out = (float*)d_out;                  // [T*8 weights][T*8 indices]

    float* scores;
    cudaGetSymbolAddress((void**)&scores, g_scores);

    dim3 ggrid(NEXP / BN, TOK / BM);
    gemm_sigmoid_kernel<<<ggrid, 256>>>(x, wght, bias, scores);

    gate_topk_kernel<<<TOK / 8, 256>>>(scores, out, out + (size_t)TOK * TOPK);
}

// round 7
// speedup vs baseline: 1.3819x; 1.3819x over previous
#include <cuda_runtime.h>
#include <cuda_bf16.h>
#include <cfloat>
#include <cstdint>

// Problem constants
#define TOK   8192
#define DIM   7168
#define NEXP  256
#define TOPKG 4
#define TOPK  8
#define RSCALE 2.5f

// GEMM tiling
#define BM 128
#define BN 128
#define BK 32
#define NCH (DIM / BK)          // 224 K-chunks
#define ROWB 80                 // bytes per panel row: 32 bf16 = 64B + 16B pad
#define PANELB (128 * ROWB)     // 10240 B per split panel
#define STAGEB (6 * PANELB)     // A0,A1,A2,B0,B1,B2 = 61440 B
#define NSTAGE 3
#define SMEM_BYTES (NSTAGE * STAGEB)   // 184320 B

// scratch: bias-added sigmoid scores [T, E]
__device__ float g_scores[(size_t)TOK * NEXP];

// ---------------------------------------------------------------------------
// helpers
// ---------------------------------------------------------------------------
__device__ __forceinline__ uint32_t smem_u32(const void* p) {
    uint32_t a;
    asm("{ .reg .u64 t; cvta.to.shared.u64 t, %1; cvt.u32.u64 %0, t; }"
        : "=r"(a) : "l"(p));
    return a;
}
__device__ __forceinline__ void ldsm_x4(uint32_t* r, uint32_t addr) {
    asm volatile("ldmatrix.sync.aligned.m8n8.x4.shared.b16 {%0,%1,%2,%3}, [%4];"
                 : "=r"(r[0]), "=r"(r[1]), "=r"(r[2]), "=r"(r[3]) : "r"(addr));
}
__device__ __forceinline__ void mma_bf16(float* c, const uint32_t* a, const uint32_t* b) {
    asm volatile(
        "mma.sync.aligned.m16n8k16.row.col.f32.bf16.bf16.f32 "
        "{%0,%1,%2,%3}, {%4,%5,%6,%7}, {%8,%9}, {%0,%1,%2,%3};"
        : "+f"(c[0]), "+f"(c[1]), "+f"(c[2]), "+f"(c[3])
        : "r"(a[0]), "r"(a[1]), "r"(a[2]), "r"(a[3]), "r"(b[0]), "r"(b[1]));
}

// split one float4 into three bf16x2-pair stores (b0+b1+b2 == x up to 2^-25)
__device__ __forceinline__ void split_store4(char* base, uint32_t off, float4 v) {
    __nv_bfloat162 p0 = __floats2bfloat162_rn(v.x, v.y);
    __nv_bfloat162 p1 = __floats2bfloat162_rn(v.z, v.w);
    float2 u0 = __bfloat1622float2(p0);
    float2 u1 = __bfloat1622float2(p1);
    float4 r1 = make_float4(v.x - u0.x, v.y - u0.y, v.z - u1.x, v.w - u1.y);
    __nv_bfloat162 q0 = __floats2bfloat162_rn(r1.x, r1.y);
    __nv_bfloat162 q1 = __floats2bfloat162_rn(r1.z, r1.w);
    float2 w0 = __bfloat1622float2(q0);
    float2 w1 = __bfloat1622float2(q1);
    __nv_bfloat162 s0 = __floats2bfloat162_rn(r1.x - w0.x, r1.y - w0.y);
    __nv_bfloat162 s1 = __floats2bfloat162_rn(r1.z - w1.x, r1.w - w1.y);
    *reinterpret_cast<uint2*>(base + off) =
        make_uint2(*reinterpret_cast<uint32_t*>(&p0), *reinterpret_cast<uint32_t*>(&p1));
    *reinterpret_cast<uint2*>(base + PANELB + off) =
        make_uint2(*reinterpret_cast<uint32_t*>(&q0), *reinterpret_cast<uint32_t*>(&q1));
    *reinterpret_cast<uint2*>(base + 2 * PANELB + off) =
        make_uint2(*reinterpret_cast<uint32_t*>(&s0), *reinterpret_cast<uint32_t*>(&s1));
}

// ---------------------------------------------------------------------------
// Kernel 1: bf16 3-split 6-term GEMM with per-chunk RN containment
// 256 threads, warps 2(M) x 4(N), warp tile 64x32, per-warp 4x4 mma tiles.
// Local TC accumulator is zeroed every K=32 chunk and folded into persistent
// fp32 registers with RN adds — bounds tensor-core internal rounding drift.
// ---------------------------------------------------------------------------
__global__ __launch_bounds__(256, 1)
void gemm_mma_kernel(const float* __restrict__ X,
                     const float* __restrict__ W,
                     const float* __restrict__ bias,
                     float* __restrict__ S)
{
    extern __shared__ char sm[];
    const int tid  = threadIdx.x;
    const int wid  = tid >> 5, lane = tid & 31;
    const int g    = lane >> 2, tig = lane & 3;
    const int wm   = wid >> 2,  wn  = wid & 3;
    const int m0   = blockIdx.y * BM;
    const int n0   = blockIdx.x * BN;
    const uint32_t sb = smem_u32(sm);

    // ldmatrix per-thread base offsets (within a panel)
    const int t8 = lane >> 3;       // 0..3
    const int r8 = lane & 7;
    const uint32_t a_base =
        (uint32_t)((wm * 64 + (t8 & 1) * 8 + r8) * ROWB + (t8 >> 1) * 16);
    const uint32_t b_base =
        (uint32_t)((wn * 32 + (t8 >> 1) * 8 + r8) * ROWB + (t8 & 1) * 16);

    // producer coords
    const int pr = tid >> 3, pq = tid & 7;
    const uint32_t p_off = (uint32_t)(pr * ROWB + pq * 8);

    float acc[4][4][4];
#pragma unroll
    for (int i = 0; i < 4; i++)
#pragma unroll
        for (int j = 0; j < 4; j++)
#pragma unroll
            for (int k = 0; k < 4; k++) acc[i][j][k] = 0.f;

    float4 R[8];   // LDG buffer

    auto ldg_chunk = [&](int c) {
        const int k0 = c * BK;
#pragma unroll
        for (int i = 0; i < 4; i++) {
            R[i]     = *reinterpret_cast<const float4*>(
                X + (size_t)(m0 + pr + 32 * i) * DIM + k0 + pq * 4);
            R[i + 4] = *reinterpret_cast<const float4*>(
                W + (size_t)(n0 + pr + 32 * i) * DIM + k0 + pq * 4);
        }
    };
    auto sts_chunk = [&](int s) {
        char* ab = sm + s * STAGEB;
        char* bb = ab + 3 * PANELB;
#pragma unroll
        for (int i = 0; i < 4; i++) {
            split_store4(ab, p_off + (uint32_t)(32 * i) * ROWB, R[i]);
            split_store4(bb, p_off + (uint32_t)(32 * i) * ROWB, R[i + 4]);
        }
    };

    // prologue
    ldg_chunk(0);
    sts_chunk(0);
    ldg_chunk(1);

    for (int c = 0; c < NCH; c++) {
        __syncthreads();
        if (c + 1 < NCH) sts_chunk((c + 1) % NSTAGE);
        if (c + 2 < NCH) ldg_chunk(c + 2);

        const uint32_t stage = sb + (c % NSTAGE) * STAGEB;
        const uint32_t apan = stage;
        const uint32_t bpan = stage + 3 * PANELB;

        // process warp tile in two M-halves to bound register pressure
#pragma unroll
        for (int half = 0; half < 2; half++) {
            float la[2][4][4];
#pragma unroll
            for (int a = 0; a < 2; a++)
#pragma unroll
                for (int b = 0; b < 4; b++)
#pragma unroll
                    for (int k = 0; k < 4; k++) la[a][b][k] = 0.f;

#pragma unroll
            for (int ks = 0; ks < 2; ks++) {
                const uint32_t ko = (uint32_t)(ks * 32);
                // all 3 B splits for this k-step
                uint32_t Bf[3][2][4];
#pragma unroll
                for (int j = 0; j < 3; j++)
#pragma unroll
                    for (int p = 0; p < 2; p++)
                        ldsm_x4(Bf[j][p],
                                bpan + (uint32_t)j * PANELB + b_base + p * (16 * ROWB) + ko);

                // i = A split; keep terms with i + j <= 2
#pragma unroll
                for (int i = 0; i < 3; i++) {
                    uint32_t Af[2][4];
#pragma unroll
                    for (int mtl = 0; mtl < 2; mtl++)
                        ldsm_x4(Af[mtl],
                                apan + (uint32_t)i * PANELB + a_base +
                                (half * 2 + mtl) * (16 * ROWB) + ko);
#pragma unroll
                    for (int j = 0; j < 3; j++) {
                        if (i + j <= 2) {
#pragma unroll
                            for (int mtl = 0; mtl < 2; mtl++)
#pragma unroll
                                for (int nt = 0; nt < 4; nt++)
                                    mma_bf16(la[mtl][nt], Af[mtl],
                                             &Bf[j][nt >> 1][(nt & 1) * 2]);
                        }
                    }
                }
            }
            // RN fold into persistent accumulators
#pragma unroll
            for (int mtl = 0; mtl < 2; mtl++)
#pragma unroll
                for (int nt = 0; nt < 4; nt++)
#pragma unroll
                    for (int k = 0; k < 4; k++)
                        acc[half * 2 + mtl][nt][k] += la[mtl][nt][k];
        }
    }

    // ---- epilogue: sigmoid + bias -> S
#pragma unroll
    for (int mt = 0; mt < 4; mt++) {
        const int row0 = m0 + wm * 64 + mt * 16 + g;
#pragma unroll
        for (int nt = 0; nt < 4; nt++) {
            const int ncol = n0 + wn * 32 + nt * 8 + tig * 2;
            const float b0 = bias[ncol], b1 = bias[ncol + 1];
            float2 v0, v1;
            v0.x = 1.0f / (1.0f + expf(-acc[mt][nt][0])) + b0;
            v0.y = 1.0f / (1.0f + expf(-acc[mt][nt][1])) + b1;
            v1.x = 1.0f / (1.0f + expf(-acc[mt][nt][2])) + b0;
            v1.y = 1.0f / (1.0f + expf(-acc[mt][nt][3])) + b1;
            *reinterpret_cast<float2*>(S + (size_t)row0 * NEXP + ncol) = v0;
            *reinterpret_cast<float2*>(S + (size_t)(row0 + 8) * NEXP + ncol) = v1;
        }
    }
}

// ---------------------------------------------------------------------------
// Kernel 2: per-token gating (unchanged from passing version)
// ---------------------------------------------------------------------------
__global__ __launch_bounds__(256)
void gate_topk_kernel(const float* __restrict__ S,
                      float* __restrict__ outW,
                      float* __restrict__ outI)
{
    const unsigned FULL = 0xffffffffu;
    const int warp = threadIdx.x >> 5;
    const int lane = threadIdx.x & 31;
    const int token = blockIdx.x * 8 + warp;
    if (token >= TOK) return;

    float v[8];
    {
        const float4* p = reinterpret_cast<const float4*>(
            S + (size_t)token * NEXP + lane * 8);
        float4 a = p[0], b = p[1];
        v[0]=a.x; v[1]=a.y; v[2]=a.z; v[3]=a.w;
        v[4]=b.x; v[5]=b.y; v[6]=b.z; v[7]=b.w;
    }

    float m1 = -FLT_MAX, m2 = -FLT_MAX;
#pragma unroll
    for (int j = 0; j < 8; j++) {
        float x = v[j];
        if (x > m1) { m2 = m1; m1 = x; }
        else if (x > m2) { m2 = x; }
    }
#pragma unroll
    for (int off = 2; off >= 1; off >>= 1) {
        float o1 = __shfl_down_sync(FULL, m1, off, 4);
        float o2 = __shfl_down_sync(FULL, m2, off, 4);
        float n1 = fmaxf(m1, o1);
        float n2 = fmaxf(fminf(m1, o1), fmaxf(m2, o2));
        m1 = n1; m2 = n2;
    }
    float gscore = m1 + m2;

    const int myg = lane >> 2;
    float mygs = __shfl_sync(FULL, gscore, myg * 4);
    int rank = 0;
#pragma unroll
    for (int g = 0; g < 8; g++) {
        float gs = __shfl_sync(FULL, gscore, g * 4);
        if (gs > mygs || (gs == mygs && g < myg)) rank++;
    }
    bool sel = (rank < TOPKG);

    float w[8];
#pragma unroll
    for (int j = 0; j < 8; j++) w[j] = sel ? v[j] : 0.0f;

    for (int r = 0; r < TOPK; r++) {
        float bv = w[0]; int bi = lane * 8;
#pragma unroll
        for (int j = 1; j < 8; j++) {
            int idx = lane * 8 + j;
            if (w[j] > bv) { bv = w[j]; bi = idx; }
        }
#pragma unroll
        for (int o = 16; o > 0; o >>= 1) {
            float ov = __shfl_xor_sync(FULL, bv, o);
            int   oi = __shfl_xor_sync(FULL, bi, o);
            if (ov > bv || (ov == bv && oi < bi)) { bv = ov; bi = oi; }
        }
        int owner = bi >> 3;
        float orig = 0.f;
        if (lane == owner) {
            orig = v[bi & 7];
            w[bi & 7] = -FLT_MAX;
        }
        orig = __shfl_sync(FULL, orig, owner);
        if (lane == r) {
            outW[(size_t)token * TOPK + r] = orig * RSCALE;
            outI[(size_t)token * TOPK + r] = (float)bi;
        }
    }
}

// ---------------------------------------------------------------------------
extern "C" void kernel_launch(void* const* d_in, const int* in_sizes, int n_in,
                              void* d_out, int out_size)
{
    const float* x    = (const float*)d_in[0];
    const float* wght = (const float*)d_in[1];
    const float* bias = (const float*)d_in[2];
    float* out = (float*)d_out;

    float* scores;
    cudaGetSymbolAddress((void**)&scores, g_scores);

    cudaFuncSetAttribute(gemm_mma_kernel,
                         cudaFuncAttributeMaxDynamicSharedMemorySize, SMEM_BYTES);

    dim3 grid(NEXP / BN, TOK / BM);
    gemm_mma_kernel<<<grid, 256, SMEM_BYTES>>>(x, wght, bias, scores);

    gate_topk_kernel<<<TOK / 8, 256>>>(scores, out, out + (size_t)TOK * TOPK);
}